// round 6
// baseline (speedup 1.0000x reference)
#include <cuda_runtime.h>
#include <cstdint>

#define NTOK   32768
#define DF     32
#define NS_ITERS 2
#define PWARPS 2              // warps per block; warp = 4 tokens; block = 8 tokens

// Output layout (float offsets): base | fiber | connection | generators
#define OUT_FIBER 16777216ull
#define OUT_CONN  50331648ull
#define OUT_GEN   50593792ull

typedef unsigned long long u64;

// ---------------------------------------------------------------------------
// f32x2 packed-math helpers
// ---------------------------------------------------------------------------
__device__ __forceinline__ void ffma2(u64& d, u64 a, u64 b) {
    asm("fma.rn.f32x2 %0, %1, %2, %0;" : "+l"(d) : "l"(a), "l"(b));
}
__device__ __forceinline__ u64 ffma2r(u64 a, u64 b, u64 c) {
    u64 r;
    asm("fma.rn.f32x2 %0, %1, %2, %3;" : "=l"(r) : "l"(a), "l"(b), "l"(c));
    return r;
}
__device__ __forceinline__ u64 fadd2(u64 a, u64 b) {
    u64 r;
    asm("add.rn.f32x2 %0, %1, %2;" : "=l"(r) : "l"(a), "l"(b));
    return r;
}
__device__ __forceinline__ u64 pack2(float lo, float hi) {
    u64 r;
    asm("mov.b64 %0, {%1, %2};" : "=l"(r) : "f"(lo), "f"(hi));
    return r;
}
__device__ __forceinline__ float2 unpack2(u64 v) {
    float2 f;
    asm("mov.b64 {%0, %1}, %2;" : "=f"(f.x), "=f"(f.y) : "l"(v));
    return f;
}

// ---------------------------------------------------------------------------
// One Newton-Schulz iteration, fused: Z = 1.5*X - 0.5 * X * (X^T X), in-place.
// Lane owns columns (2c, 2c+1) of its half-warp's token pair (f32x2 packed).
// ---------------------------------------------------------------------------
template<bool LAST>
__device__ __forceinline__ void ns_iter(u64* __restrict__ B, int c,
                                        float* __restrict__ d0,
                                        float* __restrict__ d1)
{
    u64 y0[DF], y1[DF];
    #pragma unroll
    for (int i = 0; i < DF; i++) { y0[i] = 0ull; y1[i] = 0ull; }

    // ---- Y = X^T X: columns 2c, 2c+1 ----------------------------------
    #pragma unroll 1
    for (int k = 0; k < DF; k++) {
        const ulonglong2* row = reinterpret_cast<const ulonglong2*>(B + k * DF);
        ulonglong2 xk = *reinterpret_cast<const ulonglong2*>(B + k * DF + 2 * c);
        #pragma unroll
        for (int q = 0; q < 16; q++) {
            ulonglong2 v = row[q];
            ffma2(y0[2 * q + 0], v.x, xk.x);
            ffma2(y0[2 * q + 1], v.y, xk.x);
            ffma2(y1[2 * q + 0], v.x, xk.y);
            ffma2(y1[2 * q + 1], v.y, xk.y);
        }
    }

    const u64 NH = pack2(-0.5f, -0.5f);
    const u64 TH = pack2( 1.5f,  1.5f);

    // ---- Z = 1.5 X - 0.5 X*Y (row i fully read before written) --------
    #pragma unroll 1
    for (int i = 0; i < DF; i++) {
        const ulonglong2* row = reinterpret_cast<const ulonglong2*>(B + i * DF);
        ulonglong2 own = *reinterpret_cast<const ulonglong2*>(B + i * DF + 2 * c);
        u64 a0 = 0ull, b0 = 0ull, a1 = 0ull, b1 = 0ull;
        #pragma unroll
        for (int q = 0; q < 16; q += 2) {
            ulonglong2 v = row[q];
            ulonglong2 w = row[q + 1];
            ffma2(a0, v.x, y0[2 * q + 0]); ffma2(a0, v.y, y0[2 * q + 1]);
            ffma2(b0, w.x, y0[2 * q + 2]); ffma2(b0, w.y, y0[2 * q + 3]);
            ffma2(a1, v.x, y1[2 * q + 0]); ffma2(a1, v.y, y1[2 * q + 1]);
            ffma2(b1, w.x, y1[2 * q + 2]); ffma2(b1, w.y, y1[2 * q + 3]);
        }
        u64 z0 = ffma2r(own.x, TH, ffma2r(fadd2(a0, b0), NH, 0ull));
        u64 z1 = ffma2r(own.y, TH, ffma2r(fadd2(a1, b1), NH, 0ull));
        if (LAST) {
            float2 f0 = unpack2(z0);                  // (tokE, tokO) col 2c
            float2 f1 = unpack2(z1);                  // (tokE, tokO) col 2c+1
            *reinterpret_cast<float2*>(d0 + i * DF + 2 * c) = make_float2(f0.x, f1.x);
            *reinterpret_cast<float2*>(d1 + i * DF + 2 * c) = make_float2(f0.y, f1.y);
        } else {
            ulonglong2 z; z.x = z0; z.y = z1;
            *reinterpret_cast<ulonglong2*>(B + i * DF + 2 * c) = z;
        }
    }
    __syncwarp();
}

// ---------------------------------------------------------------------------
// Fused kernel: polar factor (Newton-Schulz) + base/connection gathers +
// generators passthrough. Block = 2 warps = 8 tokens.
// ---------------------------------------------------------------------------
__global__ void __launch_bounds__(PWARPS * 32)
fused_kernel(const int* __restrict__ tokens,
             const float* __restrict__ base_w,
             const float* __restrict__ fiber_w,
             const float* __restrict__ conn_w,
             const float* __restrict__ gens,
             float* __restrict__ out)
{
    __shared__ u64 sm[PWARPS][2][DF * DF];   // 16KB per warp

    const int tid  = threadIdx.x;
    const int warp = tid >> 5;
    const int lane = tid & 31;
    const int h    = lane >> 4;
    const int c    = lane & 15;
    const int tokb_blk = blockIdx.x * (PWARPS * 4);       // 8 tokens per block
    const int tokb     = tokb_blk + warp * 4;

    u64* B = sm[warp][h];

    // ---- fiber load: half h fills its pair's matrix -------------------
    const int tE = tokens[tokb + 2 * h + 0];
    const int tO = tokens[tokb + 2 * h + 1];
    const float* sE = fiber_w + (size_t)tE * (DF * DF);
    const float* sO = fiber_w + (size_t)tO * (DF * DF);

    #pragma unroll 1
    for (int r = 0; r < DF; r++) {
        float2 vE = *reinterpret_cast<const float2*>(sE + r * DF + 2 * c);
        float2 vO = *reinterpret_cast<const float2*>(sO + r * DF + 2 * c);
        ulonglong2 p;
        p.x = pack2(vE.x, vO.x);
        p.y = pack2(vE.y, vO.y);
        *reinterpret_cast<ulonglong2*>(B + r * DF + 2 * c) = p;
    }

    // ---- base gather for this block's 8 tokens (overlaps with compute
    //      across warps; DRAM is <10% utilized) -------------------------
    {
        const float4* bw = reinterpret_cast<const float4*>(base_w);
        float4*       bo = reinterpret_cast<float4*>(out);
        #pragma unroll 1
        for (int j = 0; j < 16; j++) {
            int idx = tid + 64 * j;              // 0..1023
            int tk  = idx >> 7;                  // token 0..7
            int e   = idx & 127;                 // float4 elem in row
            int t   = tokens[tokb_blk + tk];
            bo[(size_t)(tokb_blk + tk) * 128 + e] = bw[(size_t)t * 128 + e];
        }
        if (tid < 16) {
            int tk = tid >> 1, e = tid & 1;
            int t  = tokens[tokb_blk + tk];
            const float4* cs = reinterpret_cast<const float4*>(conn_w);
            float4*       cd = reinterpret_cast<float4*>(out + OUT_CONN);
            cd[(size_t)(tokb_blk + tk) * 2 + e] = cs[(size_t)t * 2 + e];
        }
        if (blockIdx.x == 0) {                   // generators: 2048 float4
            const float4* gs = reinterpret_cast<const float4*>(gens);
            float4*       gd = reinterpret_cast<float4*>(out + OUT_GEN);
            #pragma unroll
            for (int i = 0; i < 32; i++) gd[tid + 64 * i] = gs[tid + 64 * i];
        }
    }
    __syncwarp();

    // ---- Newton-Schulz iterations --------------------------------------
    float* d0 = out + OUT_FIBER + (size_t)(tokb + 2 * h) * (DF * DF);
    float* d1 = d0 + DF * DF;

    #pragma unroll 1
    for (int it = 0; it < NS_ITERS - 1; it++)
        ns_iter<false>(B, c, d0, d1);
    ns_iter<true>(B, c, d0, d1);
}

// ---------------------------------------------------------------------------
extern "C" void kernel_launch(void* const* d_in, const int* in_sizes, int n_in,
                              void* d_out, int out_size)
{
    const int*   tokens  = (const int*)  d_in[0];
    const float* base_w  = (const float*)d_in[1];
    const float* fiber_w = (const float*)d_in[2];
    const float* conn_w  = (const float*)d_in[3];
    const float* gens    = (const float*)d_in[4];
    float* out = (float*)d_out;

    fused_kernel<<<NTOK / (PWARPS * 4), PWARPS * 32>>>(
        tokens, base_w, fiber_w, conn_w, gens, out);
}

// round 7
// speedup vs baseline: 1.1237x; 1.1237x over previous
#include <cuda_runtime.h>
#include <cstdint>

#define NTOK   32768
#define DF     32
#define NS_ITERS 2
#define PWARPS 2              // warps per polar block; each warp = 4 tokens

// Output layout (float offsets): base | fiber | connection | generators
#define OUT_FIBER 16777216ull
#define OUT_CONN  50331648ull
#define OUT_GEN   50593792ull

typedef unsigned long long u64;

// ---------------------------------------------------------------------------
// f32x2 packed-math helpers
// ---------------------------------------------------------------------------
__device__ __forceinline__ void ffma2(u64& d, u64 a, u64 b) {
    asm("fma.rn.f32x2 %0, %1, %2, %0;" : "+l"(d) : "l"(a), "l"(b));
}
__device__ __forceinline__ u64 ffma2r(u64 a, u64 b, u64 c) {
    u64 r;
    asm("fma.rn.f32x2 %0, %1, %2, %3;" : "=l"(r) : "l"(a), "l"(b), "l"(c));
    return r;
}
__device__ __forceinline__ u64 fadd2(u64 a, u64 b) {
    u64 r;
    asm("add.rn.f32x2 %0, %1, %2;" : "=l"(r) : "l"(a), "l"(b));
    return r;
}
__device__ __forceinline__ u64 pack2(float lo, float hi) {
    u64 r;
    asm("mov.b64 %0, {%1, %2};" : "=l"(r) : "f"(lo), "f"(hi));
    return r;
}
__device__ __forceinline__ float2 unpack2(u64 v) {
    float2 f;
    asm("mov.b64 {%0, %1}, %2;" : "=f"(f.x), "=f"(f.y) : "l"(v));
    return f;
}

// ---------------------------------------------------------------------------
// Kernel 1: gathers (base, connection) + generators passthrough
// ---------------------------------------------------------------------------
__global__ void gather_copy_kernel(const int* __restrict__ tokens,
                                   const float* __restrict__ base_w,
                                   const float* __restrict__ conn_w,
                                   const float* __restrict__ gens,
                                   float* __restrict__ out)
{
    int b   = blockIdx.x;
    int tid = threadIdx.x;
    if (b < NTOK) {
        int t = tokens[b];
        const float4* src = reinterpret_cast<const float4*>(base_w) + (size_t)t * 128;
        float4*       dst = reinterpret_cast<float4*>(out)          + (size_t)b * 128;
        dst[tid] = src[tid];
        if (tid < 2) {
            const float4* cs = reinterpret_cast<const float4*>(conn_w) + (size_t)t * 2;
            float4*       cd = reinterpret_cast<float4*>(out + OUT_CONN) + (size_t)b * 2;
            cd[tid] = cs[tid];
        }
    } else {
        const float4* gs = reinterpret_cast<const float4*>(gens);
        float4*       gd = reinterpret_cast<float4*>(out + OUT_GEN);
        #pragma unroll
        for (int i = 0; i < 16; i++) gd[tid + 128 * i] = gs[tid + 128 * i];
    }
}

// ---------------------------------------------------------------------------
// One Newton-Schulz iteration, fused: Z = 1.5*X - 0.5 * X * (X^T X), in-place.
// Lane owns columns (2c, 2c+1) of its half-warp's token pair (f32x2 packed).
// unroll 2 on k/i: adjacent iterations are independent -> dual LDS/FFMA2
// streams so shared-memory latency hides under the other stream's math.
// ---------------------------------------------------------------------------
template<bool LAST>
__device__ __forceinline__ void ns_iter(u64* __restrict__ B, int c,
                                        float* __restrict__ d0,
                                        float* __restrict__ d1)
{
    u64 y0[DF], y1[DF];
    #pragma unroll
    for (int i = 0; i < DF; i++) { y0[i] = 0ull; y1[i] = 0ull; }

    // ---- Y = X^T X: columns 2c, 2c+1 ----------------------------------
    #pragma unroll 2
    for (int k = 0; k < DF; k++) {
        const ulonglong2* row = reinterpret_cast<const ulonglong2*>(B + k * DF);
        ulonglong2 xk = *reinterpret_cast<const ulonglong2*>(B + k * DF + 2 * c);
        #pragma unroll
        for (int q = 0; q < 16; q++) {
            ulonglong2 v = row[q];
            ffma2(y0[2 * q + 0], v.x, xk.x);
            ffma2(y0[2 * q + 1], v.y, xk.x);
            ffma2(y1[2 * q + 0], v.x, xk.y);
            ffma2(y1[2 * q + 1], v.y, xk.y);
        }
    }

    const u64 NH = pack2(-0.5f, -0.5f);
    const u64 TH = pack2( 1.5f,  1.5f);

    // ---- Z = 1.5 X - 0.5 X*Y (row i fully read before written) --------
    #pragma unroll 2
    for (int i = 0; i < DF; i++) {
        const ulonglong2* row = reinterpret_cast<const ulonglong2*>(B + i * DF);
        ulonglong2 own = *reinterpret_cast<const ulonglong2*>(B + i * DF + 2 * c);
        u64 a0 = 0ull, b0 = 0ull, a1 = 0ull, b1 = 0ull;
        #pragma unroll
        for (int q = 0; q < 16; q += 2) {
            ulonglong2 v = row[q];
            ulonglong2 w = row[q + 1];
            ffma2(a0, v.x, y0[2 * q + 0]); ffma2(a0, v.y, y0[2 * q + 1]);
            ffma2(b0, w.x, y0[2 * q + 2]); ffma2(b0, w.y, y0[2 * q + 3]);
            ffma2(a1, v.x, y1[2 * q + 0]); ffma2(a1, v.y, y1[2 * q + 1]);
            ffma2(b1, w.x, y1[2 * q + 2]); ffma2(b1, w.y, y1[2 * q + 3]);
        }
        u64 z0 = ffma2r(own.x, TH, ffma2r(fadd2(a0, b0), NH, 0ull));
        u64 z1 = ffma2r(own.y, TH, ffma2r(fadd2(a1, b1), NH, 0ull));
        if (LAST) {
            float2 f0 = unpack2(z0);                  // (tokE, tokO) col 2c
            float2 f1 = unpack2(z1);                  // (tokE, tokO) col 2c+1
            *reinterpret_cast<float2*>(d0 + i * DF + 2 * c) = make_float2(f0.x, f1.x);
            *reinterpret_cast<float2*>(d1 + i * DF + 2 * c) = make_float2(f0.y, f1.y);
        } else {
            ulonglong2 z; z.x = z0; z.y = z1;
            *reinterpret_cast<ulonglong2*>(B + i * DF + 2 * c) = z;
        }
    }
    __syncwarp();
}

// ---------------------------------------------------------------------------
// Kernel 2: polar factor. Warp = 4 tokens (2 f32x2 pairs, one per half-warp).
// No launch_bounds reg cap (R5 showed the cap causes spills -> L2 traffic).
// ---------------------------------------------------------------------------
__global__ void __launch_bounds__(PWARPS * 32)
polar_kernel(const int* __restrict__ tokens,
             const float* __restrict__ fiber_w,
             float* __restrict__ out)
{
    __shared__ u64 sm[PWARPS][2][DF * DF];   // 16KB per warp

    const int warp = threadIdx.x >> 5;
    const int lane = threadIdx.x & 31;
    const int h    = lane >> 4;
    const int c    = lane & 15;
    const int tokb = (blockIdx.x * PWARPS + warp) * 4;

    u64* B = sm[warp][h];

    const int tE = tokens[tokb + 2 * h + 0];
    const int tO = tokens[tokb + 2 * h + 1];
    const float* sE = fiber_w + (size_t)tE * (DF * DF);
    const float* sO = fiber_w + (size_t)tO * (DF * DF);

    #pragma unroll 1
    for (int r = 0; r < DF; r++) {
        float2 vE = *reinterpret_cast<const float2*>(sE + r * DF + 2 * c);
        float2 vO = *reinterpret_cast<const float2*>(sO + r * DF + 2 * c);
        ulonglong2 p;
        p.x = pack2(vE.x, vO.x);
        p.y = pack2(vE.y, vO.y);
        *reinterpret_cast<ulonglong2*>(B + r * DF + 2 * c) = p;
    }
    __syncwarp();

    float* d0 = out + OUT_FIBER + (size_t)(tokb + 2 * h) * (DF * DF);
    float* d1 = d0 + DF * DF;

    #pragma unroll 1
    for (int it = 0; it < NS_ITERS - 1; it++)
        ns_iter<false>(B, c, d0, d1);
    ns_iter<true>(B, c, d0, d1);
}

// ---------------------------------------------------------------------------
extern "C" void kernel_launch(void* const* d_in, const int* in_sizes, int n_in,
                              void* d_out, int out_size)
{
    const int*   tokens  = (const int*)  d_in[0];
    const float* base_w  = (const float*)d_in[1];
    const float* fiber_w = (const float*)d_in[2];
    const float* conn_w  = (const float*)d_in[3];
    const float* gens    = (const float*)d_in[4];
    float* out = (float*)d_out;

    gather_copy_kernel<<<NTOK + 1, 128>>>(tokens, base_w, conn_w, gens, out);
    polar_kernel<<<NTOK / 4 / PWARPS, PWARPS * 32>>>(tokens, fiber_w, out);
}